// round 1
// baseline (speedup 1.0000x reference)
#include <cuda_runtime.h>
#include <math.h>

#define PI_F 3.14159265358979323846

static const int B = 32, C = 4, H = 512, W = 512;

// per batch: m00,m01,m02, m10,m11,m12, im00,im01,im02, im10,im11,im12
__device__ float g_mats[32 * 12];

__device__ __forceinline__ float clampf_(float v, float lo, float hi) {
    return fminf(fmaxf(v, lo), hi);
}

__global__ void build_mats_kernel(const float* __restrict__ fc2,
                                  float* __restrict__ out_mat,
                                  float* __restrict__ out_inv) {
    int b = threadIdx.x;
    if (b >= 32) return;
    float f0 = fc2[b * 7 + 0];
    float f1 = fc2[b * 7 + 1];
    float f2 = fc2[b * 7 + 2];
    float f3 = fc2[b * 7 + 3];
    float f4 = fc2[b * 7 + 4];
    float f5 = fc2[b * 7 + 5];
    float f6 = fc2[b * 7 + 6];

    float theta = clampf_(f0 * 0.3f, -1.f, 1.f) * (float)PI_F;
    float sx = clampf_(f1 * 0.3f + 1.0f, 0.f, 5.f);
    float sy = clampf_(f2 * 0.3f + 1.0f, 0.f, 5.f);
    float tx = f3 * 0.3f;
    float ty = f4 * 0.3f;
    float shxy = clampf_(f5 * 0.3f, -1.f, 1.f) * (float)PI_F;
    float shyx = clampf_(f6 * 0.3f, -1.f, 1.f) * (float)PI_F;

    // compose in double for safety
    double c = cos((double)theta), s = sin((double)theta);
    double dsx = sx, dsy = sy;
    double a  = dsx * c + (double)shxy * dsy * s;
    double bb = -dsx * s + (double)shxy * dsy * c;
    double d  = (double)shyx * dsx * c + dsy * s;
    double e  = -(double)shyx * dsx * s + dsy * c;

    // mat = [[a,bb,tx],[d,e,ty],[0,0,1]]
    out_mat[b * 9 + 0] = (float)a;
    out_mat[b * 9 + 1] = (float)bb;
    out_mat[b * 9 + 2] = tx;
    out_mat[b * 9 + 3] = (float)d;
    out_mat[b * 9 + 4] = (float)e;
    out_mat[b * 9 + 5] = ty;
    out_mat[b * 9 + 6] = 0.f;
    out_mat[b * 9 + 7] = 0.f;
    out_mat[b * 9 + 8] = 1.f;

    double det = a * e - bb * d;
    double ia  = e / det;
    double ib  = -bb / det;
    double itx = (bb * (double)ty - e * (double)tx) / det;
    double id  = -d / det;
    double ie  = a / det;
    double ity = (d * (double)tx - a * (double)ty) / det;

    out_inv[b * 9 + 0] = (float)ia;
    out_inv[b * 9 + 1] = (float)ib;
    out_inv[b * 9 + 2] = (float)itx;
    out_inv[b * 9 + 3] = (float)id;
    out_inv[b * 9 + 4] = (float)ie;
    out_inv[b * 9 + 5] = (float)ity;
    out_inv[b * 9 + 6] = 0.f;
    out_inv[b * 9 + 7] = 0.f;
    out_inv[b * 9 + 8] = 1.f;

    float* gm = &g_mats[b * 12];
    gm[0] = (float)a;  gm[1] = (float)bb; gm[2]  = tx;
    gm[3] = (float)d;  gm[4] = (float)e;  gm[5]  = ty;
    gm[6] = (float)ia; gm[7] = (float)ib; gm[8]  = (float)itx;
    gm[9] = (float)id; gm[10] = (float)ie; gm[11] = (float)ity;
}

__global__ __launch_bounds__(256)
void affine_kernel(const float* __restrict__ src,
                   float* __restrict__ out_trans,
                   float* __restrict__ out_grid,
                   float* __restrict__ out_invgrid) {
    const int b = blockIdx.y;
    const int pix = blockIdx.x * blockDim.x + threadIdx.x;  // 0 .. H*W-1
    const int h = pix >> 9;
    const int w = pix & 511;

    const float* __restrict__ m = &g_mats[b * 12];
    float m0 = __ldg(&m[0]), m1 = __ldg(&m[1]), m2 = __ldg(&m[2]);
    float m3 = __ldg(&m[3]), m4 = __ldg(&m[4]), m5 = __ldg(&m[5]);
    float i0 = __ldg(&m[6]), i1 = __ldg(&m[7]), i2 = __ldg(&m[8]);
    float i3 = __ldg(&m[9]), i4 = __ldg(&m[10]), i5 = __ldg(&m[11]);

    const float x = (2.0f * (float)w + 1.0f) * (1.0f / (float)W) - 1.0f;
    const float y = (2.0f * (float)h + 1.0f) * (1.0f / (float)H) - 1.0f;

    const float gx = fmaf(m0, x, fmaf(m1, y, m2));
    const float gy = fmaf(m3, x, fmaf(m4, y, m5));
    const float igx = fmaf(i0, x, fmaf(i1, y, i2));
    const float igy = fmaf(i3, x, fmaf(i4, y, i5));

    const size_t gidx = (size_t)b * (H * W) + (size_t)pix;
    reinterpret_cast<float2*>(out_grid)[gidx]    = make_float2(gx, gy);
    reinterpret_cast<float2*>(out_invgrid)[gidx] = make_float2(igx, igy);

    // bilinear sample with zero padding
    const float ixf = ((gx + 1.0f) * (float)W - 1.0f) * 0.5f;
    const float iyf = ((gy + 1.0f) * (float)H - 1.0f) * 0.5f;
    const float x0f = floorf(ixf);
    const float y0f = floorf(iyf);
    const float wx = ixf - x0f;
    const float wy = iyf - y0f;
    const int x0 = (int)x0f;
    const int y0 = (int)y0f;
    const int x1 = x0 + 1;
    const int y1 = y0 + 1;

    const float vx0 = (x0 >= 0 && x0 < W) ? 1.0f : 0.0f;
    const float vx1 = (x1 >= 0 && x1 < W) ? 1.0f : 0.0f;
    const float vy0 = (y0 >= 0 && y0 < H) ? 1.0f : 0.0f;
    const float vy1 = (y1 >= 0 && y1 < H) ? 1.0f : 0.0f;

    const int cx0 = min(max(x0, 0), W - 1);
    const int cx1 = min(max(x1, 0), W - 1);
    const int cy0 = min(max(y0, 0), H - 1);
    const int cy1 = min(max(y1, 0), H - 1);

    const float w00 = (1.0f - wx) * (1.0f - wy) * vx0 * vy0;
    const float w01 = wx * (1.0f - wy) * vx1 * vy0;
    const float w10 = (1.0f - wx) * wy * vx0 * vy1;
    const float w11 = wx * wy * vx1 * vy1;

    const size_t off00 = (size_t)cy0 * W + cx0;
    const size_t off01 = (size_t)cy0 * W + cx1;
    const size_t off10 = (size_t)cy1 * W + cx0;
    const size_t off11 = (size_t)cy1 * W + cx1;

    const float* __restrict__ sb = src + (size_t)b * C * H * W;
    float* __restrict__ ob = out_trans + (size_t)b * C * H * W;

#pragma unroll
    for (int c = 0; c < C; c++) {
        const float* __restrict__ img = sb + (size_t)c * (H * W);
        float v00 = __ldg(&img[off00]);
        float v01 = __ldg(&img[off01]);
        float v10 = __ldg(&img[off10]);
        float v11 = __ldg(&img[off11]);
        float r = fmaf(v00, w00, fmaf(v01, w01, fmaf(v10, w10, v11 * w11)));
        ob[(size_t)c * (H * W) + pix] = r;
    }
}

extern "C" void kernel_launch(void* const* d_in, const int* in_sizes, int n_in,
                              void* d_out, int out_size) {
    const float* src = (const float*)d_in[0];
    const float* fc2 = (const float*)d_in[1];
    float* out = (float*)d_out;

    // output layout: transformed | mat | inv_mat | grid | inv_grid
    const size_t n_trans = (size_t)B * C * H * W;          // 33,554,432
    const size_t n_mat = (size_t)B * 9;                    // 288
    const size_t n_grid = (size_t)B * H * W * 2;           // 16,777,216

    float* out_trans = out;
    float* out_mat   = out + n_trans;
    float* out_inv   = out_mat + n_mat;
    float* out_grid  = out_inv + n_mat;
    float* out_igrid = out_grid + n_grid;

    build_mats_kernel<<<1, 32>>>(fc2, out_mat, out_inv);

    dim3 grid((H * W) / 256, B);
    affine_kernel<<<grid, 256>>>(src, out_trans, out_grid, out_igrid);
}

// round 2
// speedup vs baseline: 1.5913x; 1.5913x over previous
#include <cuda_runtime.h>
#include <math.h>

#define PI_F 3.14159265358979323846

static const int B = 32, C = 4, H = 512, W = 512;

// per batch: m00,m01,m02, m10,m11,m12, im00,im01,im02, im10,im11,im12
__device__ float g_mats[32 * 12];

__device__ __forceinline__ float clampf_(float v, float lo, float hi) {
    return fminf(fmaxf(v, lo), hi);
}

__global__ void build_mats_kernel(const float* __restrict__ fc2,
                                  float* __restrict__ out_mat,
                                  float* __restrict__ out_inv) {
    int b = threadIdx.x;
    if (b >= 32) return;
    float f0 = fc2[b * 7 + 0];
    float f1 = fc2[b * 7 + 1];
    float f2 = fc2[b * 7 + 2];
    float f3 = fc2[b * 7 + 3];
    float f4 = fc2[b * 7 + 4];
    float f5 = fc2[b * 7 + 5];
    float f6 = fc2[b * 7 + 6];

    float theta = clampf_(f0 * 0.3f, -1.f, 1.f) * (float)PI_F;
    float sx = clampf_(f1 * 0.3f + 1.0f, 0.f, 5.f);
    float sy = clampf_(f2 * 0.3f + 1.0f, 0.f, 5.f);
    float tx = f3 * 0.3f;
    float ty = f4 * 0.3f;
    float shxy = clampf_(f5 * 0.3f, -1.f, 1.f) * (float)PI_F;
    float shyx = clampf_(f6 * 0.3f, -1.f, 1.f) * (float)PI_F;

    double c = cos((double)theta), s = sin((double)theta);
    double dsx = sx, dsy = sy;
    double a  = dsx * c + (double)shxy * dsy * s;
    double bb = -dsx * s + (double)shxy * dsy * c;
    double d  = (double)shyx * dsx * c + dsy * s;
    double e  = -(double)shyx * dsx * s + dsy * c;

    out_mat[b * 9 + 0] = (float)a;
    out_mat[b * 9 + 1] = (float)bb;
    out_mat[b * 9 + 2] = tx;
    out_mat[b * 9 + 3] = (float)d;
    out_mat[b * 9 + 4] = (float)e;
    out_mat[b * 9 + 5] = ty;
    out_mat[b * 9 + 6] = 0.f;
    out_mat[b * 9 + 7] = 0.f;
    out_mat[b * 9 + 8] = 1.f;

    double det = a * e - bb * d;
    double ia  = e / det;
    double ib  = -bb / det;
    double itx = (bb * (double)ty - e * (double)tx) / det;
    double id  = -d / det;
    double ie  = a / det;
    double ity = (d * (double)tx - a * (double)ty) / det;

    out_inv[b * 9 + 0] = (float)ia;
    out_inv[b * 9 + 1] = (float)ib;
    out_inv[b * 9 + 2] = (float)itx;
    out_inv[b * 9 + 3] = (float)id;
    out_inv[b * 9 + 4] = (float)ie;
    out_inv[b * 9 + 5] = (float)ity;
    out_inv[b * 9 + 6] = 0.f;
    out_inv[b * 9 + 7] = 0.f;
    out_inv[b * 9 + 8] = 1.f;

    float* gm = &g_mats[b * 12];
    gm[0] = (float)a;  gm[1] = (float)bb; gm[2]  = tx;
    gm[3] = (float)d;  gm[4] = (float)e;  gm[5]  = ty;
    gm[6] = (float)ia; gm[7] = (float)ib; gm[8]  = (float)itx;
    gm[9] = (float)id; gm[10] = (float)ie; gm[11] = (float)ity;
}

// ---------------------------------------------------------------------------
// Streaming kernel: writes grid + inv_grid, 2 pixels per thread (float4 stores)
// ---------------------------------------------------------------------------
__global__ __launch_bounds__(256)
void grid_kernel(float* __restrict__ out_grid,
                 float* __restrict__ out_invgrid) {
    const int HW2 = (H * W) / 2;                 // pixel-pairs per batch
    const int t = blockIdx.x * blockDim.x + threadIdx.x;  // global pair id
    const int b = t >> 17;                       // / (512*512/2)
    const int rem = t & (HW2 - 1);
    const int pix = rem << 1;                    // even pixel index
    const int h = pix >> 9;
    const int w = pix & 511;

    const float* __restrict__ m = &g_mats[b * 12];
    float m0 = m[0], m1 = m[1], m2 = m[2];
    float m3 = m[3], m4 = m[4], m5 = m[5];
    float i0 = m[6], i1 = m[7], i2 = m[8];
    float i3 = m[9], i4 = m[10], i5 = m[11];

    const float x0 = (2.0f * (float)w + 1.0f) * (1.0f / (float)W) - 1.0f;
    const float y  = (2.0f * (float)h + 1.0f) * (1.0f / (float)H) - 1.0f;
    const float dx = 2.0f / (float)W;

    float base_x = fmaf(m1, y, m2);
    float base_y = fmaf(m4, y, m5);
    float ibase_x = fmaf(i1, y, i2);
    float ibase_y = fmaf(i4, y, i5);

    float gx0 = fmaf(m0, x0, base_x);
    float gy0 = fmaf(m3, x0, base_y);
    float gx1 = fmaf(m0, x0 + dx, base_x);
    float gy1 = fmaf(m3, x0 + dx, base_y);

    float ix0 = fmaf(i0, x0, ibase_x);
    float iy0 = fmaf(i3, x0, ibase_y);
    float ix1 = fmaf(i0, x0 + dx, ibase_x);
    float iy1 = fmaf(i3, x0 + dx, ibase_y);

    reinterpret_cast<float4*>(out_grid)[t]    = make_float4(gx0, gy0, gx1, gy1);
    reinterpret_cast<float4*>(out_invgrid)[t] = make_float4(ix0, iy0, ix1, iy1);
}

// ---------------------------------------------------------------------------
// Sampler: square-ish warp tiles (8 wide x 4 tall) to keep the rotated source
// footprint compact -> fewer L1 wavefronts per gather.
// Block covers 32x8 pixels (4 warps across x, 2 across y).
// ---------------------------------------------------------------------------
__global__ __launch_bounds__(256)
void sample_kernel(const float* __restrict__ src,
                   float* __restrict__ out_trans) {
    const int tid = threadIdx.x;
    const int lane = tid & 31;
    const int warp = tid >> 5;
    const int lx = lane & 7;        // 0..7
    const int ly = lane >> 3;       // 0..3
    const int wx = warp & 3;        // 0..3
    const int wy = warp >> 2;       // 0..1

    const int w = blockIdx.x * 32 + wx * 8 + lx;
    const int h = blockIdx.y * 8 + wy * 4 + ly;
    const int b = blockIdx.z;
    const int pix = h * W + w;

    const float* __restrict__ m = &g_mats[b * 12];
    float m0 = m[0], m1 = m[1], m2 = m[2];
    float m3 = m[3], m4 = m[4], m5 = m[5];

    const float x = (2.0f * (float)w + 1.0f) * (1.0f / (float)W) - 1.0f;
    const float y = (2.0f * (float)h + 1.0f) * (1.0f / (float)H) - 1.0f;

    const float gx = fmaf(m0, x, fmaf(m1, y, m2));
    const float gy = fmaf(m3, x, fmaf(m4, y, m5));

    const float ixf = ((gx + 1.0f) * (float)W - 1.0f) * 0.5f;
    const float iyf = ((gy + 1.0f) * (float)H - 1.0f) * 0.5f;
    const float x0f = floorf(ixf);
    const float y0f = floorf(iyf);
    const float wxf = ixf - x0f;
    const float wyf = iyf - y0f;
    const int x0 = (int)x0f;
    const int y0 = (int)y0f;
    const int x1 = x0 + 1;
    const int y1 = y0 + 1;

    const float vx0 = (x0 >= 0 && x0 < W) ? 1.0f : 0.0f;
    const float vx1 = (x1 >= 0 && x1 < W) ? 1.0f : 0.0f;
    const float vy0 = (y0 >= 0 && y0 < H) ? 1.0f : 0.0f;
    const float vy1 = (y1 >= 0 && y1 < H) ? 1.0f : 0.0f;

    const int cx0 = min(max(x0, 0), W - 1);
    const int cx1 = min(max(x1, 0), W - 1);
    const int cy0 = min(max(y0, 0), H - 1);
    const int cy1 = min(max(y1, 0), H - 1);

    const float w00 = (1.0f - wxf) * (1.0f - wyf) * vx0 * vy0;
    const float w01 = wxf * (1.0f - wyf) * vx1 * vy0;
    const float w10 = (1.0f - wxf) * wyf * vx0 * vy1;
    const float w11 = wxf * wyf * vx1 * vy1;

    const int off00 = cy0 * W + cx0;
    const int off01 = cy0 * W + cx1;
    const int off10 = cy1 * W + cx0;
    const int off11 = cy1 * W + cx1;

    const float* __restrict__ sb = src + (size_t)b * C * H * W;
    float* __restrict__ ob = out_trans + (size_t)b * C * H * W;

#pragma unroll
    for (int c = 0; c < C; c++) {
        const float* __restrict__ img = sb + (size_t)c * (H * W);
        float v00 = __ldg(&img[off00]);
        float v01 = __ldg(&img[off01]);
        float v10 = __ldg(&img[off10]);
        float v11 = __ldg(&img[off11]);
        float r = fmaf(v00, w00, fmaf(v01, w01, fmaf(v10, w10, v11 * w11)));
        ob[(size_t)c * (H * W) + pix] = r;
    }
}

extern "C" void kernel_launch(void* const* d_in, const int* in_sizes, int n_in,
                              void* d_out, int out_size) {
    const float* src = (const float*)d_in[0];
    const float* fc2 = (const float*)d_in[1];
    float* out = (float*)d_out;

    // output layout: transformed | mat | inv_mat | grid | inv_grid
    const size_t n_trans = (size_t)B * C * H * W;          // 33,554,432
    const size_t n_mat = (size_t)B * 9;                    // 288
    const size_t n_grid = (size_t)B * H * W * 2;           // 16,777,216

    float* out_trans = out;
    float* out_mat   = out + n_trans;
    float* out_inv   = out_mat + n_mat;
    float* out_grid  = out_inv + n_mat;
    float* out_igrid = out_grid + n_grid;

    build_mats_kernel<<<1, 32>>>(fc2, out_mat, out_inv);

    // grids: B*H*W/2 pixel-pairs, 256 threads/block
    const int n_pairs = B * H * W / 2;            // 4,194,304
    grid_kernel<<<n_pairs / 256, 256>>>(out_grid, out_igrid);

    dim3 sgrid(W / 32, H / 8, B);
    sample_kernel<<<sgrid, 256>>>(src, out_trans);
}

// round 3
// speedup vs baseline: 1.7664x; 1.1101x over previous
#include <cuda_runtime.h>
#include <math.h>

#define PI_F 3.14159265358979323846f

static const int B = 32, C = 4, H = 512, W = 512;

__device__ __forceinline__ float clampf_(float v, float lo, float hi) {
    return fminf(fmaxf(v, lo), hi);
}

// ---------------------------------------------------------------------------
// One fused kernel:
//  - per-thread recompute of fwd/inv affine matrices from fc2 (fp32, ~50 ops)
//  - writes grid + inv_grid (float2, 64B warp-row segments — full sectors)
//  - bilinear-samples 4 channels with zero padding folded into tap weights
//  - one elected thread per batch writes mat / inv_mat
// Warp tile: 8 wide x 4 tall (compact rotated source footprint -> few L1
// wavefronts per gather). Block covers 32x8 pixels.
// ---------------------------------------------------------------------------
__global__ __launch_bounds__(256)
void fused_affine_kernel(const float* __restrict__ src,
                         const float* __restrict__ fc2,
                         float* __restrict__ out_trans,
                         float* __restrict__ out_mat,
                         float* __restrict__ out_inv,
                         float* __restrict__ out_grid,
                         float* __restrict__ out_invgrid) {
    const int b = blockIdx.z;

    // --- rebuild matrices in registers (uniform across block; L1-broadcast) ---
    const float* __restrict__ f = fc2 + b * 7;
    float f0 = __ldg(&f[0]), f1 = __ldg(&f[1]), f2 = __ldg(&f[2]);
    float f3 = __ldg(&f[3]), f4 = __ldg(&f[4]), f5 = __ldg(&f[5]);
    float f6 = __ldg(&f[6]);

    const float theta = clampf_(f0 * 0.3f, -1.f, 1.f) * PI_F;
    const float sx = clampf_(f1 * 0.3f + 1.0f, 0.f, 5.f);
    const float sy = clampf_(f2 * 0.3f + 1.0f, 0.f, 5.f);
    const float tx = f3 * 0.3f;
    const float ty = f4 * 0.3f;
    const float shxy = clampf_(f5 * 0.3f, -1.f, 1.f) * PI_F;
    const float shyx = clampf_(f6 * 0.3f, -1.f, 1.f) * PI_F;

    const float c = cosf(theta), s = sinf(theta);
    // mat = trn @ shr @ scl @ rot = [[a,bb,tx],[d,e,ty],[0,0,1]]
    const float a  = fmaf(shxy * sy, s, sx * c);
    const float bb = fmaf(shxy * sy, c, -sx * s);
    const float d  = fmaf(shyx * sx, c, sy * s);
    const float e  = fmaf(-shyx * sx, s, sy * c);

    const float det = fmaf(a, e, -bb * d);
    const float rdet = 1.0f / det;
    const float ia  = e * rdet;
    const float ib  = -bb * rdet;
    const float itx = fmaf(bb, ty, -e * tx) * rdet;
    const float id  = -d * rdet;
    const float ie  = a * rdet;
    const float ity = fmaf(d, tx, -a * ty) * rdet;

    if (blockIdx.x == 0 && blockIdx.y == 0 && threadIdx.x == 0) {
        float* om = out_mat + b * 9;
        om[0] = a;  om[1] = bb; om[2] = tx;
        om[3] = d;  om[4] = e;  om[5] = ty;
        om[6] = 0.f; om[7] = 0.f; om[8] = 1.f;
        float* oi = out_inv + b * 9;
        oi[0] = ia; oi[1] = ib; oi[2] = itx;
        oi[3] = id; oi[4] = ie; oi[5] = ity;
        oi[6] = 0.f; oi[7] = 0.f; oi[8] = 1.f;
    }

    // --- pixel coordinates: 8x4 warp tile, 32x8 block tile ---
    const int tid = threadIdx.x;
    const int lane = tid & 31;
    const int warp = tid >> 5;
    const int lx = lane & 7;
    const int ly = lane >> 3;
    const int wx = warp & 3;
    const int wy = warp >> 2;

    const int w = blockIdx.x * 32 + wx * 8 + lx;
    const int h = blockIdx.y * 8 + wy * 4 + ly;
    const int pix = h * W + w;

    const float x = (2.0f * (float)w + 1.0f) * (1.0f / (float)W) - 1.0f;
    const float y = (2.0f * (float)h + 1.0f) * (1.0f / (float)H) - 1.0f;

    const float gx = fmaf(a, x, fmaf(bb, y, tx));
    const float gy = fmaf(d, x, fmaf(e, y, ty));
    const float igx = fmaf(ia, x, fmaf(ib, y, itx));
    const float igy = fmaf(id, x, fmaf(ie, y, ity));

    const size_t gidx = (size_t)b * (H * W) + (size_t)pix;
    reinterpret_cast<float2*>(out_grid)[gidx]    = make_float2(gx, gy);
    reinterpret_cast<float2*>(out_invgrid)[gidx] = make_float2(igx, igy);

    // --- bilinear sample with zero padding ---
    const float ixf = ((gx + 1.0f) * (float)W - 1.0f) * 0.5f;
    const float iyf = ((gy + 1.0f) * (float)H - 1.0f) * 0.5f;
    const float x0f = floorf(ixf);
    const float y0f = floorf(iyf);
    const float wxf = ixf - x0f;
    const float wyf = iyf - y0f;
    const int x0 = (int)x0f;
    const int y0 = (int)y0f;
    const int x1 = x0 + 1;
    const int y1 = y0 + 1;

    const float vx0 = (x0 >= 0 && x0 < W) ? 1.0f : 0.0f;
    const float vx1 = (x1 >= 0 && x1 < W) ? 1.0f : 0.0f;
    const float vy0 = (y0 >= 0 && y0 < H) ? 1.0f : 0.0f;
    const float vy1 = (y1 >= 0 && y1 < H) ? 1.0f : 0.0f;

    const int cx0 = min(max(x0, 0), W - 1);
    const int cx1 = min(max(x1, 0), W - 1);
    const int cy0 = min(max(y0, 0), H - 1);
    const int cy1 = min(max(y1, 0), H - 1);

    const float w00 = (1.0f - wxf) * (1.0f - wyf) * vx0 * vy0;
    const float w01 = wxf * (1.0f - wyf) * vx1 * vy0;
    const float w10 = (1.0f - wxf) * wyf * vx0 * vy1;
    const float w11 = wxf * wyf * vx1 * vy1;

    const int off00 = cy0 * W + cx0;
    const int off01 = cy0 * W + cx1;
    const int off10 = cy1 * W + cx0;
    const int off11 = cy1 * W + cx1;

    const float* __restrict__ sb = src + (size_t)b * C * H * W;
    float* __restrict__ ob = out_trans + (size_t)b * C * H * W;

#pragma unroll
    for (int ch = 0; ch < C; ch++) {
        const float* __restrict__ img = sb + (size_t)ch * (H * W);
        float v00 = __ldg(&img[off00]);
        float v01 = __ldg(&img[off01]);
        float v10 = __ldg(&img[off10]);
        float v11 = __ldg(&img[off11]);
        float r = fmaf(v00, w00, fmaf(v01, w01, fmaf(v10, w10, v11 * w11)));
        ob[(size_t)ch * (H * W) + pix] = r;
    }
}

extern "C" void kernel_launch(void* const* d_in, const int* in_sizes, int n_in,
                              void* d_out, int out_size) {
    const float* src = (const float*)d_in[0];
    const float* fc2 = (const float*)d_in[1];
    float* out = (float*)d_out;

    // output layout: transformed | mat | inv_mat | grid | inv_grid
    const size_t n_trans = (size_t)B * C * H * W;          // 33,554,432
    const size_t n_mat = (size_t)B * 9;                    // 288
    const size_t n_grid = (size_t)B * H * W * 2;           // 16,777,216

    float* out_trans = out;
    float* out_mat   = out + n_trans;
    float* out_inv   = out_mat + n_mat;
    float* out_grid  = out_inv + n_mat;
    float* out_igrid = out_grid + n_grid;

    dim3 grid(W / 32, H / 8, B);
    fused_affine_kernel<<<grid, 256>>>(src, fc2, out_trans, out_mat, out_inv,
                                       out_grid, out_igrid);
}